// round 14
// baseline (speedup 1.0000x reference)
#include <cuda_runtime.h>
#include <cuda_fp16.h>
#include <cstdint>

// ===================== device scratch (no allocation) =====================
__device__ float g_off[8 * 18 * 128 * 128];   // offset conv output
__device__ __align__(16) __half g_xp[8 * 16384 * 64];  // x packed [b][y][x][c] fp16
__device__ uint2 g_w16m[4 * 9 * 4 * 8 * 8];   // main W fp16: [j][t][tig][gid][nt8]
__device__ uint2 g_ow16[4 * 9 * 4 * 8 * 4];   // offset W fp16: [j][t][tig][gid][nt4]

// ===================== helpers =====================
__device__ __forceinline__ uint32_t packf16(float2 s) {
    uint32_t r;   // lo half = s.x
    asm("cvt.rn.f16x2.f32 %0, %1, %2;" : "=r"(r) : "f"(s.y), "f"(s.x));
    return r;
}
__device__ __forceinline__ uint32_t hsub2(uint32_t a, uint32_t b) {
    uint32_t d;
    asm("sub.rn.f16x2 %0, %1, %2;" : "=r"(d) : "r"(a), "r"(b));
    return d;
}
__device__ __forceinline__ uint32_t hfma2(uint32_t a, uint32_t b, uint32_t c) {
    uint32_t d;
    asm("fma.rn.f16x2 %0, %1, %2, %3;" : "=r"(d) : "r"(a), "r"(b), "r"(c));
    return d;
}
__device__ __forceinline__ uint32_t duplo(uint32_t a) {
    uint32_t d;
    asm("prmt.b32 %0, %1, %1, 0x1010;" : "=r"(d) : "r"(a));
    return d;
}
__device__ __forceinline__ uint32_t duphi(uint32_t a) {
    uint32_t d;
    asm("prmt.b32 %0, %1, %1, 0x3232;" : "=r"(d) : "r"(a));
    return d;
}
__device__ __forceinline__ float h2lof(uint32_t h) {
    __half2 v = *(__half2*)&h;
    return __low2float(v);
}
__device__ __forceinline__ void mma16(float* d,
                                      uint32_t a0, uint32_t a1, uint32_t a2, uint32_t a3,
                                      uint32_t b0, uint32_t b1) {
    asm volatile(
        "mma.sync.aligned.m16n8k16.row.col.f32.f16.f16.f32 "
        "{%0,%1,%2,%3}, {%4,%5,%6,%7}, {%8,%9}, {%0,%1,%2,%3};"
        : "+f"(d[0]), "+f"(d[1]), "+f"(d[2]), "+f"(d[3])
        : "r"(a0), "r"(a1), "r"(a2), "r"(a3), "r"(b0), "r"(b1));
}

// bilinear sample of a channel QUAD (uint2 = 2x half2), quad-major tile
// layout [quad][pos] (stride 30 rows). R12-validated bank behavior.
__device__ __forceinline__ uint2 bsq(const uint2* __restrict__ xt_q,
                                     const float* __restrict__ xgq,
                                     uint2 m) {
    int val = (int)m.y;
    uint32_t wyd = duplo(m.x), wxd = duphi(m.x);
    if (val >= 0) {
        uint2 c0 = xt_q[val], c1 = xt_q[val + 1];
        uint2 c2 = xt_q[val + 30], c3 = xt_q[val + 31];
        uint32_t rx0 = hfma2(hsub2(c1.x, c0.x), wxd, c0.x);
        uint32_t rx1 = hfma2(hsub2(c3.x, c2.x), wxd, c2.x);
        uint32_t ry0 = hfma2(hsub2(c1.y, c0.y), wxd, c0.y);
        uint32_t ry1 = hfma2(hsub2(c3.y, c2.y), wxd, c2.y);
        uint2 r;
        r.x = hfma2(hsub2(rx1, rx0), wyd, rx0);
        r.y = hfma2(hsub2(ry1, ry0), wyd, ry0);
        return r;
    }
    // rare fallback: fp32 masked global bilinear on 4 channels
    float wy = h2lof(wyd), wx = h2lof(wxd);
    float oy = 1.f - wy, ox = 1.f - wx;
    float w00 = oy * ox, w01 = oy * wx, w10 = wy * ox, w11 = wy * wx;
    int iy = ((val >> 8) & 0xff) - 2;
    int ix = (val & 0xff) - 2;
    bool m00 = ((unsigned)iy < 128u) & ((unsigned)ix < 128u);
    bool m01 = ((unsigned)iy < 128u) & ((unsigned)(ix + 1) < 128u);
    bool m10 = ((unsigned)(iy + 1) < 128u) & ((unsigned)ix < 128u);
    bool m11 = ((unsigned)(iy + 1) < 128u) & ((unsigned)(ix + 1) < 128u);
    int i00 = iy * 128 + ix;
    float v[4];
#pragma unroll
    for (int c = 0; c < 4; c++) {
        const float* g = xgq + c * 16384;
        v[c] = w00 * (m00 ? g[i00] : 0.f) + w01 * (m01 ? g[i00 + 1] : 0.f)
             + w10 * (m10 ? g[i00 + 128] : 0.f) + w11 * (m11 ? g[i00 + 129] : 0.f);
    }
    uint2 r;
    r.x = packf16(make_float2(v[0], v[1]));
    r.y = packf16(make_float2(v[2], v[3]));
    return r;
}

// ===================== prep: pack x to fp16 NHWC =====================
__global__ __launch_bounds__(256) void xpack_kernel(const float* __restrict__ x) {
    __shared__ uint32_t sm[64 * 32];    // [pixel][c2]
    int tid = threadIdx.x;
    int bp = blockIdx.x * 64;
    int b = blockIdx.y;
    const float* xb = x + (size_t)b * 64 * 16384;
    for (int i = tid; i < 2048; i += 256) {
        int c2 = i >> 6, p = i & 63;
        float v0 = xb[(2 * c2) * 16384 + bp + p];
        float v1 = xb[(2 * c2 + 1) * 16384 + bp + p];
        sm[p * 32 + c2] = packf16(make_float2(v0, v1));
    }
    __syncthreads();
    uint4* dst = (uint4*)(g_xp + ((size_t)b * 16384 + bp) * 64);
    const uint4* src = (const uint4*)sm;
    for (int i = tid; i < 512; i += 256) dst[i] = src[i];
}

// ===================== prep: weight layouts =====================
__global__ void wprep_kernel(const float* __restrict__ dw,
                             const float* __restrict__ ow) {
    int i = blockIdx.x * 256 + threadIdx.x;
    if (i < 9216) {            // main W: [j][t][tig][gid][nt], quad-channel slots
        int j = i / 2304, r = i - j * 2304;
        int t = r >> 8, r2 = r & 255;
        int tg = r2 >> 6, r3 = r2 & 63;
        int gd = r3 >> 3, nt = r3 & 7;
        int o = nt * 8 + gd;
        int c0 = j * 16 + 4 * tg;
        __half2 h0 = __floats2half2_rn(dw[o * 576 + c0 * 9 + t],
                                       dw[o * 576 + (c0 + 1) * 9 + t]);
        __half2 h1 = __floats2half2_rn(dw[o * 576 + (c0 + 2) * 9 + t],
                                       dw[o * 576 + (c0 + 3) * 9 + t]);
        uint2 v;
        v.x = *(uint32_t*)&h0;
        v.y = *(uint32_t*)&h1;
        g_w16m[i] = v;
    }
    if (i < 4608) {            // offset W: [j][t][tig][gid][nt4], o = nt*8+gid
        int j = i / 1152, r = i - j * 1152;
        int t = r >> 7, r2 = r & 127;
        int tg = r2 >> 5, r3 = r2 & 31;
        int gd = r3 >> 2, nt = r3 & 3;
        int o = nt * 8 + gd;
        int c0 = j * 16 + 4 * tg;
        float w0 = 0.f, w1 = 0.f, w2 = 0.f, w3 = 0.f;
        if (o < 18) {
            w0 = ow[o * 576 + c0 * 9 + t];
            w1 = ow[o * 576 + (c0 + 1) * 9 + t];
            w2 = ow[o * 576 + (c0 + 2) * 9 + t];
            w3 = ow[o * 576 + (c0 + 3) * 9 + t];
        }
        uint2 v;
        v.x = packf16(make_float2(w0, w1));
        v.y = packf16(make_float2(w2, w3));
        g_ow16[i] = v;
    }
}

// ===================== stage 1: offset conv, quad fp16 mma16 =====================
// Block 16x16 px, 8 warps; warp = px rows {2w, 2w+1}. N=24 (18 used), K=16ch x tap.
// Quad-major tile [q][18x18], staged from packed g_xp.
__global__ __launch_bounds__(256, 2) void offconv_kernel(
    const float* __restrict__ x, const float* __restrict__ ob)
{
    __shared__ uint2 xtq[1296];         // [quad][18x18]
    __shared__ uint2 wh[1152];          // [t][tig][gid][nt4]

    int tid = threadIdx.x, w = tid >> 5, lane = tid & 31;
    int gid = lane >> 2, tig = lane & 3;
    int b = blockIdx.z, ty = blockIdx.y * 16, tx = blockIdx.x * 16;
    const __half* xpb = g_xp + (size_t)b * 16384 * 64;

    float acc0[3][4], acc1[3][4];
#pragma unroll
    for (int n = 0; n < 3; n++)
#pragma unroll
        for (int i = 0; i < 4; i++) { acc0[n][i] = 0.f; acc1[n][i] = 0.f; }

    for (int j = 0; j < 4; j++) {
        __syncthreads();
        for (int t = tid; t < 324; t += 256) {
            int rr = t / 18, cl = t - rr * 18;
            int gy = ty - 1 + rr, gx = tx - 1 + cl;
            uint4 v0 = make_uint4(0u, 0u, 0u, 0u), v1 = v0;
            if ((unsigned)gy < 128u && (unsigned)gx < 128u) {
                const uint4* s = (const uint4*)(xpb + (size_t)(gy * 128 + gx) * 64 + j * 16);
                v0 = s[0]; v1 = s[1];
            }
            xtq[t]        = make_uint2(v0.x, v0.y);
            xtq[324 + t]  = make_uint2(v0.z, v0.w);
            xtq[648 + t]  = make_uint2(v1.x, v1.y);
            xtq[972 + t]  = make_uint2(v1.z, v1.w);
        }
        for (int t = tid; t < 1152; t += 256) wh[t] = g_ow16[j * 1152 + t];
        __syncthreads();

#pragma unroll
        for (int t9 = 0; t9 < 9; t9++) {
            int dty = t9 / 3, dtx = t9 - dty * 3;
            const uint2* ap = xtq + tig * 324 + (2 * w + dty) * 18 + gid + dtx;
            uint2 A0 = ap[0], A1 = ap[8], A2 = ap[18], A3 = ap[26];

            const uint2* Bp = wh + ((t9 * 4 + tig) * 8 + gid) * 4;
            uint4 q01 = *(const uint4*)Bp;
            uint2 q2 = Bp[2];

            mma16(acc0[0], A0.x, A1.x, A0.y, A1.y, q01.x, q01.y);
            mma16(acc1[0], A2.x, A3.x, A2.y, A3.y, q01.x, q01.y);
            mma16(acc0[1], A0.x, A1.x, A0.y, A1.y, q01.z, q01.w);
            mma16(acc1[1], A2.x, A3.x, A2.y, A3.y, q01.z, q01.w);
            mma16(acc0[2], A0.x, A1.x, A0.y, A1.y, q2.x, q2.y);
            mma16(acc1[2], A2.x, A3.x, A2.y, A3.y, q2.x, q2.y);
        }
    }

    int yA = ty + 2 * w, xA = tx + gid, xB = xA + 8;
    size_t bb = (size_t)b * 18 * 16384;
#pragma unroll
    for (int nt = 0; nt < 3; nt++) {
        int o0 = nt * 8 + 2 * tig;
        if (o0 < 18) {
            float bs = ob[o0];
            float* pl = g_off + bb + (size_t)o0 * 16384;
            pl[yA * 128 + xA]       = acc0[nt][0] + bs;
            pl[yA * 128 + xB]       = acc0[nt][2] + bs;
            pl[(yA + 1) * 128 + xA] = acc1[nt][0] + bs;
            pl[(yA + 1) * 128 + xB] = acc1[nt][2] + bs;
        }
        if (o0 + 1 < 18) {
            float bs = ob[o0 + 1];
            float* pl = g_off + bb + (size_t)(o0 + 1) * 16384;
            pl[yA * 128 + xA]       = acc0[nt][1] + bs;
            pl[yA * 128 + xB]       = acc0[nt][3] + bs;
            pl[(yA + 1) * 128 + xA] = acc1[nt][1] + bs;
            pl[(yA + 1) * 128 + xB] = acc1[nt][3] + bs;
        }
    }
}

// ===================== SMEM layout main (float index) =====================
// smeta : 2304 x uint2 {packed(wy,wx), pos}                [0, 4608)
// xtq   : 4 quads x 870 uint2 (quad-major)                 [4608, 11568)
// whs   : 2304 x uint2  [t][tig][gid][nt]                  [11568, 16176)
#define SM_MT  0
#define SM_XT  4608
#define SM_WH  11568
#define SMEM_MAIN_BYTES (16176 * 4)

// ===================== stage 2: quad gather + fp16 mma16 ===================
// Block 16x16 pixels (M=256), 256 threads = 8 warps; warp = 32 px (2 m16 tiles).
// N=64. K = 16 channels x 1 tap per mma16; 4 chunks of 16 channels x 9 taps.
__global__ __launch_bounds__(256, 2) void deform_main_kernel(
    const float* __restrict__ x, const float* __restrict__ db,
    float* __restrict__ out)
{
    extern __shared__ __align__(16) float smf[];
    uint2* smeta = (uint2*)(smf + SM_MT);   // 2304
    uint2* xtq   = (uint2*)(smf + SM_XT);   // [quad][870]
    uint2* whs   = (uint2*)(smf + SM_WH);   // 2304

    int tid = threadIdx.x, w = tid >> 5, lane = tid & 31;
    int gid = lane >> 2, tig = lane & 3;
    int b = blockIdx.z, ty = blockIdx.y * 16, tx = blockIdx.x * 16;
    const float* xb = x + (size_t)b * 64 * 16384;
    const __half* xpb = g_xp + (size_t)b * 16384 * 64;

    // ---- prologue: per (tap,pixel) compact metadata ----
    for (int e = tid; e < 2304; e += 256) {
        int k = e >> 8, p = e & 255;
        int yy = ty + (p >> 4), xx = tx + (p & 15);
        float dy = g_off[((size_t)b * 18 + 2 * k) * 16384 + yy * 128 + xx];
        float dx = g_off[((size_t)b * 18 + 2 * k + 1) * 16384 + yy * 128 + xx];
        float py = (float)(yy + k / 3 - 1) + dy;
        float px = (float)(xx + k % 3 - 1) + dx;
        float fy = floorf(py), fx = floorf(px);
        float wy = py - fy, wx = px - fx;
        // clamp to [-2,128]: clamped region has all-invalid corners -> exact 0
        int iy = (int)fminf(fmaxf(fy, -2.f), 128.f);
        int ix = (int)fminf(fmaxf(fx, -2.f), 128.f);
        int ly = iy - (ty - 6), lx = ix - (tx - 6);
        int val;
        if ((unsigned)ly < 28u && (unsigned)lx < 29u)
            val = ly * 30 + lx;
        else
            val = (int)(0x80000000u | ((unsigned)(iy + 2) << 8) | (unsigned)(ix + 2));
        smeta[e] = make_uint2(packf16(make_float2(wy, wx)), (uint32_t)val);
    }

    float acc0[8][4], acc1[8][4];
#pragma unroll
    for (int n = 0; n < 8; n++)
#pragma unroll
        for (int i = 0; i < 4; i++) { acc0[n][i] = 0.f; acc1[n][i] = 0.f; }

    const int p0 = w * 32 + gid;

    for (int j = 0; j < 4; j++) {
        __syncthreads();
        // x tile: staged from packed g_xp (coalesced 32B records),
        // stored quad-major (R12-validated gather layout)
        for (int t = tid; t < 870; t += 256) {
            int rr = t / 30, cl = t - rr * 30;
            int gy = ty - 6 + rr, gx = tx - 6 + cl;
            uint4 v0 = make_uint4(0u, 0u, 0u, 0u), v1 = v0;
            if ((unsigned)gy < 128u && (unsigned)gx < 128u) {
                const uint4* s = (const uint4*)(xpb + (size_t)(gy * 128 + gx) * 64 + j * 16);
                v0 = s[0]; v1 = s[1];
            }
            xtq[t]         = make_uint2(v0.x, v0.y);
            xtq[870 + t]   = make_uint2(v0.z, v0.w);
            xtq[1740 + t]  = make_uint2(v1.x, v1.y);
            xtq[2610 + t]  = make_uint2(v1.z, v1.w);
        }
        {
            const uint4* src = (const uint4*)(g_w16m + j * 2304);
            uint4* dst = (uint4*)whs;
            for (int t = tid; t < 1152; t += 256) dst[t] = src[t];
        }
        __syncthreads();

        const uint2* xq = xtq + tig * 870;
        const float* xgq = xb + (size_t)j * 16 * 16384 + (size_t)(4 * tig) * 16384;

#pragma unroll
        for (int t = 0; t < 9; t++) {
            int ib = t * 256 + p0;
            uint2 A0 = bsq(xq, xgq, smeta[ib]);
            uint2 A1 = bsq(xq, xgq, smeta[ib + 8]);
            uint2 A2 = bsq(xq, xgq, smeta[ib + 16]);
            uint2 A3 = bsq(xq, xgq, smeta[ib + 24]);

            const uint4* Bp = (const uint4*)(whs + ((t * 4 + tig) * 8 + gid) * 8);
            uint4 q0 = Bp[0], q1 = Bp[1], q2 = Bp[2], q3 = Bp[3];

            mma16(acc0[0], A0.x, A1.x, A0.y, A1.y, q0.x, q0.y);
            mma16(acc1[0], A2.x, A3.x, A2.y, A3.y, q0.x, q0.y);
            mma16(acc0[1], A0.x, A1.x, A0.y, A1.y, q0.z, q0.w);
            mma16(acc1[1], A2.x, A3.x, A2.y, A3.y, q0.z, q0.w);
            mma16(acc0[2], A0.x, A1.x, A0.y, A1.y, q1.x, q1.y);
            mma16(acc1[2], A2.x, A3.x, A2.y, A3.y, q1.x, q1.y);
            mma16(acc0[3], A0.x, A1.x, A0.y, A1.y, q1.z, q1.w);
            mma16(acc1[3], A2.x, A3.x, A2.y, A3.y, q1.z, q1.w);
            mma16(acc0[4], A0.x, A1.x, A0.y, A1.y, q2.x, q2.y);
            mma16(acc1[4], A2.x, A3.x, A2.y, A3.y, q2.x, q2.y);
            mma16(acc0[5], A0.x, A1.x, A0.y, A1.y, q2.z, q2.w);
            mma16(acc1[5], A2.x, A3.x, A2.y, A3.y, q2.z, q2.w);
            mma16(acc0[6], A0.x, A1.x, A0.y, A1.y, q3.x, q3.y);
            mma16(acc1[6], A2.x, A3.x, A2.y, A3.y, q3.x, q3.y);
            mma16(acc0[7], A0.x, A1.x, A0.y, A1.y, q3.z, q3.w);
            mma16(acc1[7], A2.x, A3.x, A2.y, A3.y, q3.z, q3.w);
        }
    }

    // ---- epilogue: bias + relu ----
    int yA = ty + 2 * w, xA = tx + gid, xB = xA + 8;
    float* obp = out + (size_t)b * 64 * 16384;
#pragma unroll
    for (int nt = 0; nt < 8; nt++) {
        int o0 = nt * 8 + 2 * tig;
        float bs0 = db[o0], bs1 = db[o0 + 1];
        float* pl0 = obp + (size_t)o0 * 16384;
        float* pl1 = pl0 + 16384;
        pl0[yA * 128 + xA]       = fmaxf(acc0[nt][0] + bs0, 0.f);
        pl1[yA * 128 + xA]       = fmaxf(acc0[nt][1] + bs1, 0.f);
        pl0[yA * 128 + xB]       = fmaxf(acc0[nt][2] + bs0, 0.f);
        pl1[yA * 128 + xB]       = fmaxf(acc0[nt][3] + bs1, 0.f);
        pl0[(yA + 1) * 128 + xA] = fmaxf(acc1[nt][0] + bs0, 0.f);
        pl1[(yA + 1) * 128 + xA] = fmaxf(acc1[nt][1] + bs1, 0.f);
        pl0[(yA + 1) * 128 + xB] = fmaxf(acc1[nt][2] + bs0, 0.f);
        pl1[(yA + 1) * 128 + xB] = fmaxf(acc1[nt][3] + bs1, 0.f);
    }
}

// ===================== launch =====================
extern "C" void kernel_launch(void* const* d_in, const int* in_sizes, int n_in,
                              void* d_out, int out_size) {
    const float* x        = (const float*)d_in[0];  // (8,64,128,128)
    const float* offset_w = (const float*)d_in[1];  // (18,64,3,3)
    const float* offset_b = (const float*)d_in[2];  // (18,)
    const float* deform_w = (const float*)d_in[3];  // (64,64,3,3)
    const float* deform_b = (const float*)d_in[4];  // (64,)
    float* out = (float*)d_out;                     // (8,64,128,128)

    cudaFuncSetAttribute(deform_main_kernel,
                         cudaFuncAttributeMaxDynamicSharedMemorySize,
                         SMEM_MAIN_BYTES);

    xpack_kernel<<<dim3(256, 8), 256>>>(x);
    wprep_kernel<<<36, 256>>>(deform_w, offset_w);
    offconv_kernel<<<dim3(8, 8, 8), 256>>>(x, offset_b);
    deform_main_kernel<<<dim3(8, 8, 8), 256, SMEM_MAIN_BYTES>>>(x, deform_b, out);
}

// round 15
// speedup vs baseline: 1.1580x; 1.1580x over previous
#include <cuda_runtime.h>
#include <cuda_fp16.h>
#include <cstdint>

// ===================== device scratch (no allocation) =====================
__device__ float g_off[8 * 18 * 128 * 128];   // offset conv output
__device__ __align__(16) __half g_xp[8 * 16384 * 64];  // x packed [b][y][x][c] fp16
__device__ uint2 g_w16m[4 * 9 * 4 * 8 * 8];   // main W fp16 [j][t][tig][gid][nt8], tig-swizzled chunks
__device__ uint2 g_ow16[4 * 9 * 4 * 8 * 4];   // offset W fp16: [j][t][tig][gid][nt4]

// ===================== helpers =====================
__device__ __forceinline__ uint32_t packf16(float2 s) {
    uint32_t r;   // lo half = s.x
    asm("cvt.rn.f16x2.f32 %0, %1, %2;" : "=r"(r) : "f"(s.y), "f"(s.x));
    return r;
}
__device__ __forceinline__ uint32_t hsub2(uint32_t a, uint32_t b) {
    uint32_t d;
    asm("sub.rn.f16x2 %0, %1, %2;" : "=r"(d) : "r"(a), "r"(b));
    return d;
}
__device__ __forceinline__ uint32_t hfma2(uint32_t a, uint32_t b, uint32_t c) {
    uint32_t d;
    asm("fma.rn.f16x2 %0, %1, %2, %3;" : "=r"(d) : "r"(a), "r"(b), "r"(c));
    return d;
}
__device__ __forceinline__ uint32_t duplo(uint32_t a) {
    uint32_t d;
    asm("prmt.b32 %0, %1, %1, 0x1010;" : "=r"(d) : "r"(a));
    return d;
}
__device__ __forceinline__ uint32_t duphi(uint32_t a) {
    uint32_t d;
    asm("prmt.b32 %0, %1, %1, 0x3232;" : "=r"(d) : "r"(a));
    return d;
}
__device__ __forceinline__ float h2lof(uint32_t h) {
    __half2 v = *(__half2*)&h;
    return __low2float(v);
}
__device__ __forceinline__ void mma16(float* d,
                                      uint32_t a0, uint32_t a1, uint32_t a2, uint32_t a3,
                                      uint32_t b0, uint32_t b1) {
    asm volatile(
        "mma.sync.aligned.m16n8k16.row.col.f32.f16.f16.f32 "
        "{%0,%1,%2,%3}, {%4,%5,%6,%7}, {%8,%9}, {%0,%1,%2,%3};"
        : "+f"(d[0]), "+f"(d[1]), "+f"(d[2]), "+f"(d[3])
        : "r"(a0), "r"(a1), "r"(a2), "r"(a3), "r"(b0), "r"(b1));
}

// bilinear sample of channel quad `tig` at interleaved-tile position `val`.
// Tile layout: [pos][16 ch] (4 uint2 per pos); xq = tile base (uint2*) + tig.
// (R13-validated: the 4 tig-lanes of a pixel read one contiguous 32B record.)
__device__ __forceinline__ uint2 bsq(const uint2* __restrict__ xq,
                                     const float* __restrict__ xgq,
                                     uint2 m) {
    int val = (int)m.y;
    uint32_t wyd = duplo(m.x), wxd = duphi(m.x);
    if (val >= 0) {
        int i0 = val * 4;
        uint2 c0 = xq[i0], c1 = xq[i0 + 4];
        uint2 c2 = xq[i0 + 120], c3 = xq[i0 + 124];
        uint32_t rx0 = hfma2(hsub2(c1.x, c0.x), wxd, c0.x);
        uint32_t rx1 = hfma2(hsub2(c3.x, c2.x), wxd, c2.x);
        uint32_t ry0 = hfma2(hsub2(c1.y, c0.y), wxd, c0.y);
        uint32_t ry1 = hfma2(hsub2(c3.y, c2.y), wxd, c2.y);
        uint2 r;
        r.x = hfma2(hsub2(rx1, rx0), wyd, rx0);
        r.y = hfma2(hsub2(ry1, ry0), wyd, ry0);
        return r;
    }
    // rare fallback: fp32 masked global bilinear on 4 channels
    float wy = h2lof(wyd), wx = h2lof(wxd);
    float oy = 1.f - wy, ox = 1.f - wx;
    float w00 = oy * ox, w01 = oy * wx, w10 = wy * ox, w11 = wy * wx;
    int iy = ((val >> 8) & 0xff) - 2;
    int ix = (val & 0xff) - 2;
    bool m00 = ((unsigned)iy < 128u) & ((unsigned)ix < 128u);
    bool m01 = ((unsigned)iy < 128u) & ((unsigned)(ix + 1) < 128u);
    bool m10 = ((unsigned)(iy + 1) < 128u) & ((unsigned)ix < 128u);
    bool m11 = ((unsigned)(iy + 1) < 128u) & ((unsigned)(ix + 1) < 128u);
    int i00 = iy * 128 + ix;
    float v[4];
#pragma unroll
    for (int c = 0; c < 4; c++) {
        const float* g = xgq + c * 16384;
        v[c] = w00 * (m00 ? g[i00] : 0.f) + w01 * (m01 ? g[i00 + 1] : 0.f)
             + w10 * (m10 ? g[i00 + 128] : 0.f) + w11 * (m11 ? g[i00 + 129] : 0.f);
    }
    uint2 r;
    r.x = packf16(make_float2(v[0], v[1]));
    r.y = packf16(make_float2(v[2], v[3]));
    return r;
}

// ===================== prep: pack x to fp16 NHWC =====================
__global__ __launch_bounds__(256) void xpack_kernel(const float* __restrict__ x) {
    __shared__ uint32_t sm[64 * 32];    // [pixel][c2]
    int tid = threadIdx.x;
    int bp = blockIdx.x * 64;
    int b = blockIdx.y;
    const float* xb = x + (size_t)b * 64 * 16384;
    for (int i = tid; i < 2048; i += 256) {
        int c2 = i >> 6, p = i & 63;
        float v0 = xb[(2 * c2) * 16384 + bp + p];
        float v1 = xb[(2 * c2 + 1) * 16384 + bp + p];
        sm[p * 32 + c2] = packf16(make_float2(v0, v1));
    }
    __syncthreads();
    uint4* dst = (uint4*)(g_xp + ((size_t)b * 16384 + bp) * 64);
    const uint4* src = (const uint4*)sm;
    for (int i = tid; i < 512; i += 256) dst[i] = src[i];
}

// ===================== prep: weight layouts =====================
__global__ void wprep_kernel(const float* __restrict__ dw,
                             const float* __restrict__ ow) {
    int i = blockIdx.x * 256 + threadIdx.x;
    if (i < 9216) {            // main W: [j][t][tig][gid][nt], chunk ^ tig swizzle
        int j = i / 2304, r = i - j * 2304;
        int t = r >> 8, r2 = r & 255;
        int tg = r2 >> 6, r3 = r2 & 63;
        int gd = r3 >> 3, ntp = r3 & 7;
        // physical chunk ntp>>1 holds logical chunk (ntp>>1) ^ tg
        int k = (ntp >> 1) ^ tg;
        int nt = (k << 1) | (ntp & 1);
        int o = nt * 8 + gd;
        int c0 = j * 16 + 4 * tg;
        __half2 h0 = __floats2half2_rn(dw[o * 576 + c0 * 9 + t],
                                       dw[o * 576 + (c0 + 1) * 9 + t]);
        __half2 h1 = __floats2half2_rn(dw[o * 576 + (c0 + 2) * 9 + t],
                                       dw[o * 576 + (c0 + 3) * 9 + t]);
        uint2 v;
        v.x = *(uint32_t*)&h0;
        v.y = *(uint32_t*)&h1;
        g_w16m[i] = v;
    }
    if (i < 4608) {            // offset W: [j][t][tig][gid][nt4], o = nt*8+gid
        int j = i / 1152, r = i - j * 1152;
        int t = r >> 7, r2 = r & 127;
        int tg = r2 >> 5, r3 = r2 & 31;
        int gd = r3 >> 2, nt = r3 & 3;
        int o = nt * 8 + gd;
        int c0 = j * 16 + 4 * tg;
        float w0 = 0.f, w1 = 0.f, w2 = 0.f, w3 = 0.f;
        if (o < 18) {
            w0 = ow[o * 576 + c0 * 9 + t];
            w1 = ow[o * 576 + (c0 + 1) * 9 + t];
            w2 = ow[o * 576 + (c0 + 2) * 9 + t];
            w3 = ow[o * 576 + (c0 + 3) * 9 + t];
        }
        uint2 v;
        v.x = packf16(make_float2(w0, w1));
        v.y = packf16(make_float2(w2, w3));
        g_ow16[i] = v;
    }
}

// ===================== stage 1: offset conv, quad fp16 mma16 (R12 version) ====
// Block 16x16 px, 8 warps; warp = px rows {2w, 2w+1}. N=24 (18 used), K=16ch x tap.
__global__ __launch_bounds__(256, 2) void offconv_kernel(
    const float* __restrict__ x, const float* __restrict__ ob)
{
    __shared__ uint2 xtq[1296];         // [quad][18x18]
    __shared__ uint2 wh[1152];          // [t][tig][gid][nt4]

    int tid = threadIdx.x, w = tid >> 5, lane = tid & 31;
    int gid = lane >> 2, tig = lane & 3;
    int b = blockIdx.z, ty = blockIdx.y * 16, tx = blockIdx.x * 16;
    const float* xb = x + (size_t)b * 64 * 16384;

    float acc0[3][4], acc1[3][4];
#pragma unroll
    for (int n = 0; n < 3; n++)
#pragma unroll
        for (int i = 0; i < 4; i++) { acc0[n][i] = 0.f; acc1[n][i] = 0.f; }

    for (int j = 0; j < 4; j++) {
        __syncthreads();
        const float* xc = xb + (size_t)j * 16 * 16384;
        for (int t = tid; t < 1296; t += 256) {
            int q = t / 324, pos = t - q * 324;
            int rr = pos / 18, cl = pos - rr * 18;
            int gy = ty - 1 + rr, gx = tx - 1 + cl;
            uint2 v = make_uint2(0u, 0u);
            if ((unsigned)gy < 128u && (unsigned)gx < 128u) {
                const float* s = xc + 4 * q * 16384 + gy * 128 + gx;
                v.x = packf16(make_float2(s[0], s[16384]));
                v.y = packf16(make_float2(s[2 * 16384], s[3 * 16384]));
            }
            xtq[t] = v;
        }
        for (int t = tid; t < 1152; t += 256) wh[t] = g_ow16[j * 1152 + t];
        __syncthreads();

#pragma unroll
        for (int t9 = 0; t9 < 9; t9++) {
            int dty = t9 / 3, dtx = t9 - dty * 3;
            const uint2* ap = xtq + tig * 324 + (2 * w + dty) * 18 + gid + dtx;
            uint2 A0 = ap[0], A1 = ap[8], A2 = ap[18], A3 = ap[26];

            const uint2* Bp = wh + ((t9 * 4 + tig) * 8 + gid) * 4;
            uint4 q01 = *(const uint4*)Bp;
            uint2 q2 = Bp[2];

            mma16(acc0[0], A0.x, A1.x, A0.y, A1.y, q01.x, q01.y);
            mma16(acc1[0], A2.x, A3.x, A2.y, A3.y, q01.x, q01.y);
            mma16(acc0[1], A0.x, A1.x, A0.y, A1.y, q01.z, q01.w);
            mma16(acc1[1], A2.x, A3.x, A2.y, A3.y, q01.z, q01.w);
            mma16(acc0[2], A0.x, A1.x, A0.y, A1.y, q2.x, q2.y);
            mma16(acc1[2], A2.x, A3.x, A2.y, A3.y, q2.x, q2.y);
        }
    }

    int yA = ty + 2 * w, xA = tx + gid, xB = xA + 8;
    size_t bb = (size_t)b * 18 * 16384;
#pragma unroll
    for (int nt = 0; nt < 3; nt++) {
        int o0 = nt * 8 + 2 * tig;
        if (o0 < 18) {
            float bs = ob[o0];
            float* pl = g_off + bb + (size_t)o0 * 16384;
            pl[yA * 128 + xA]       = acc0[nt][0] + bs;
            pl[yA * 128 + xB]       = acc0[nt][2] + bs;
            pl[(yA + 1) * 128 + xA] = acc1[nt][0] + bs;
            pl[(yA + 1) * 128 + xB] = acc1[nt][2] + bs;
        }
        if (o0 + 1 < 18) {
            float bs = ob[o0 + 1];
            float* pl = g_off + bb + (size_t)(o0 + 1) * 16384;
            pl[yA * 128 + xA]       = acc0[nt][1] + bs;
            pl[yA * 128 + xB]       = acc0[nt][3] + bs;
            pl[(yA + 1) * 128 + xA] = acc1[nt][1] + bs;
            pl[(yA + 1) * 128 + xB] = acc1[nt][3] + bs;
        }
    }
}

// ===================== SMEM layout main (float index) =====================
// smeta : 2304 x uint2 {packed(wy,wx), pos}                [0, 4608)
// xtq   : 870 pos x 32B interleaved [pos][16ch]            [4608, 11568)
// whs   : 2304 x uint2  [t][tig][gid][nt] (chunk^tig)      [11568, 16176)
#define SM_MT  0
#define SM_XT  4608
#define SM_WH  11568
#define SMEM_MAIN_BYTES (16176 * 4)

// ===================== stage 2: quad gather + fp16 mma16 ===================
// Block 16x16 pixels (M=256), 256 threads = 8 warps; warp = 32 px (2 m16 tiles).
// N=64. K = 16 channels x 1 tap per mma16; 4 chunks of 16 channels x 9 taps.
__global__ __launch_bounds__(256, 2) void deform_main_kernel(
    const float* __restrict__ x, const float* __restrict__ db,
    float* __restrict__ out)
{
    extern __shared__ __align__(16) float smf[];
    uint2* smeta = (uint2*)(smf + SM_MT);   // 2304
    uint2* xtq   = (uint2*)(smf + SM_XT);   // [pos][quad]
    uint2* whs   = (uint2*)(smf + SM_WH);   // 2304

    int tid = threadIdx.x, w = tid >> 5, lane = tid & 31;
    int gid = lane >> 2, tig = lane & 3;
    int b = blockIdx.z, ty = blockIdx.y * 16, tx = blockIdx.x * 16;
    const float* xb = x + (size_t)b * 64 * 16384;
    const __half* xpb = g_xp + (size_t)b * 16384 * 64;

    // ---- prologue: per (tap,pixel) compact metadata ----
    for (int e = tid; e < 2304; e += 256) {
        int k = e >> 8, p = e & 255;
        int yy = ty + (p >> 4), xx = tx + (p & 15);
        float dy = g_off[((size_t)b * 18 + 2 * k) * 16384 + yy * 128 + xx];
        float dx = g_off[((size_t)b * 18 + 2 * k + 1) * 16384 + yy * 128 + xx];
        float py = (float)(yy + k / 3 - 1) + dy;
        float px = (float)(xx + k % 3 - 1) + dx;
        float fy = floorf(py), fx = floorf(px);
        float wy = py - fy, wx = px - fx;
        // clamp to [-2,128]: clamped region has all-invalid corners -> exact 0
        int iy = (int)fminf(fmaxf(fy, -2.f), 128.f);
        int ix = (int)fminf(fmaxf(fx, -2.f), 128.f);
        int ly = iy - (ty - 6), lx = ix - (tx - 6);
        int val;
        if ((unsigned)ly < 28u && (unsigned)lx < 29u)
            val = ly * 30 + lx;
        else
            val = (int)(0x80000000u | ((unsigned)(iy + 2) << 8) | (unsigned)(ix + 2));
        smeta[e] = make_uint2(packf16(make_float2(wy, wx)), (uint32_t)val);
    }

    float acc0[8][4], acc1[8][4];
#pragma unroll
    for (int n = 0; n < 8; n++)
#pragma unroll
        for (int i = 0; i < 4; i++) { acc0[n][i] = 0.f; acc1[n][i] = 0.f; }

    const int p0 = w * 32 + gid;

    for (int j = 0; j < 4; j++) {
        __syncthreads();
        // x tile: 29x30 positions x 16 ch (32B), interleaved, from packed g_xp
        for (int t = tid; t < 870; t += 256) {
            int rr = t / 30, cl = t - rr * 30;
            int gy = ty - 6 + rr, gx = tx - 6 + cl;
            uint4 v0 = make_uint4(0u, 0u, 0u, 0u), v1 = v0;
            if ((unsigned)gy < 128u && (unsigned)gx < 128u) {
                const uint4* s = (const uint4*)(xpb + (size_t)(gy * 128 + gx) * 64 + j * 16);
                v0 = s[0]; v1 = s[1];
            }
            uint4* d = (uint4*)(xtq + t * 4);
            d[0] = v0; d[1] = v1;
        }
        {
            const uint4* src = (const uint4*)(g_w16m + j * 2304);
            uint4* dst = (uint4*)whs;
            for (int t = tid; t < 1152; t += 256) dst[t] = src[t];
        }
        __syncthreads();

        const uint2* xq = xtq + tig;
        const float* xgq = xb + (size_t)j * 16 * 16384 + (size_t)(4 * tig) * 16384;

#pragma unroll
        for (int t = 0; t < 9; t++) {
            int ib = t * 256 + p0;
            uint2 A0 = bsq(xq, xgq, smeta[ib]);
            uint2 A1 = bsq(xq, xgq, smeta[ib + 8]);
            uint2 A2 = bsq(xq, xgq, smeta[ib + 16]);
            uint2 A3 = bsq(xq, xgq, smeta[ib + 24]);

            // B reads: chunk k lives at physical chunk k ^ tig (bank-despread)
            const uint4* Bp = (const uint4*)(whs + ((t * 4 + tig) * 8 + gid) * 8);
            uint4 q0 = Bp[tig];
            uint4 q1 = Bp[1 ^ tig];
            uint4 q2 = Bp[2 ^ tig];
            uint4 q3 = Bp[3 ^ tig];

            mma16(acc0[0], A0.x, A1.x, A0.y, A1.y, q0.x, q0.y);
            mma16(acc1[0], A2.x, A3.x, A2.y, A3.y, q0.x, q0.y);
            mma16(acc0[1], A0.x, A1.x, A0.y, A1.y, q0.z, q0.w);
            mma16(acc1[1], A2.x, A3.x, A2.y, A3.y, q0.z, q0.w);
            mma16(acc0[2], A0.x, A1.x, A0.y, A1.y, q1.x, q1.y);
            mma16(acc1[2], A2.x, A3.x, A2.y, A3.y, q1.x, q1.y);
            mma16(acc0[3], A0.x, A1.x, A0.y, A1.y, q1.z, q1.w);
            mma16(acc1[3], A2.x, A3.x, A2.y, A3.y, q1.z, q1.w);
            mma16(acc0[4], A0.x, A1.x, A0.y, A1.y, q2.x, q2.y);
            mma16(acc1[4], A2.x, A3.x, A2.y, A3.y, q2.x, q2.y);
            mma16(acc0[5], A0.x, A1.x, A0.y, A1.y, q2.z, q2.w);
            mma16(acc1[5], A2.x, A3.x, A2.y, A3.y, q2.z, q2.w);
            mma16(acc0[6], A0.x, A1.x, A0.y, A1.y, q3.x, q3.y);
            mma16(acc1[6], A2.x, A3.x, A2.y, A3.y, q3.x, q3.y);
            mma16(acc0[7], A0.x, A1.x, A0.y, A1.y, q3.z, q3.w);
            mma16(acc1[7], A2.x, A3.x, A2.y, A3.y, q3.z, q3.w);
        }
    }

    // ---- epilogue: bias + relu ----
    int yA = ty + 2 * w, xA = tx + gid, xB = xA + 8;
    float* obp = out + (size_t)b * 64 * 16384;
#pragma unroll
    for (int nt = 0; nt < 8; nt++) {
        int o0 = nt * 8 + 2 * tig;
        float bs0 = db[o0], bs1 = db[o0 + 1];
        float* pl0 = obp + (size_t)o0 * 16384;
        float* pl1 = pl0 + 16384;
        pl0[yA * 128 + xA]       = fmaxf(acc0[nt][0] + bs0, 0.f);
        pl1[yA * 128 + xA]       = fmaxf(acc0[nt][1] + bs1, 0.f);
        pl0[yA * 128 + xB]       = fmaxf(acc0[nt][2] + bs0, 0.f);
        pl1[yA * 128 + xB]       = fmaxf(acc0[nt][3] + bs1, 0.f);
        pl0[(yA + 1) * 128 + xA] = fmaxf(acc1[nt][0] + bs0, 0.f);
        pl1[(yA + 1) * 128 + xA] = fmaxf(acc1[nt][1] + bs1, 0.f);
        pl0[(yA + 1) * 128 + xB] = fmaxf(acc1[nt][2] + bs0, 0.f);
        pl1[(yA + 1) * 128 + xB] = fmaxf(acc1[nt][3] + bs1, 0.f);
    }
}

// ===================== launch =====================
extern "C" void kernel_launch(void* const* d_in, const int* in_sizes, int n_in,
                              void* d_out, int out_size) {
    const float* x        = (const float*)d_in[0];  // (8,64,128,128)
    const float* offset_w = (const float*)d_in[1];  // (18,64,3,3)
    const float* offset_b = (const float*)d_in[2];  // (18,)
    const float* deform_w = (const float*)d_in[3];  // (64,64,3,3)
    const float* deform_b = (const float*)d_in[4];  // (64,)
    float* out = (float*)d_out;                     // (8,64,128,128)

    cudaFuncSetAttribute(deform_main_kernel,
                         cudaFuncAttributeMaxDynamicSharedMemorySize,
                         SMEM_MAIN_BYTES);

    xpack_kernel<<<dim3(256, 8), 256>>>(x);
    wprep_kernel<<<36, 256>>>(deform_w, offset_w);
    offconv_kernel<<<dim3(8, 8, 8), 256>>>(x, offset_b);
    deform_main_kernel<<<dim3(8, 8, 8), 256, SMEM_MAIN_BYTES>>>(x, deform_b, out);
}

// round 17
// speedup vs baseline: 1.3493x; 1.1652x over previous
#include <cuda_runtime.h>
#include <cuda_fp16.h>
#include <cstdint>

// ===================== device scratch (no allocation) =====================
__device__ float g_off[8 * 18 * 128 * 128];   // offset conv output
__device__ __align__(16) __half g_xp[8 * 16384 * 64];  // x packed [b][y][x][c] fp16
__device__ uint2 g_w16m[4 * 9 * 4 * 8 * 8];   // main W fp16 [j][t][tig][gid][nt8], tig-swizzled chunks
__device__ uint2 g_ow16[4 * 9 * 4 * 8 * 4];   // offset W fp16: [j][t][tig][gid][nt4]

// ===================== helpers =====================
__device__ __forceinline__ uint32_t smem_u32(const void* p) {
    uint32_t a;
    asm("{ .reg .u64 t; cvta.to.shared.u64 t, %1; cvt.u32.u64 %0, t; }"
        : "=r"(a) : "l"(p));
    return a;
}
#define CP16(dst, src, sz) \
    asm volatile("cp.async.cg.shared.global [%0], [%1], 16, %2;" \
                 :: "r"(dst), "l"(src), "r"(sz) : "memory")
#define CPCOMMIT() asm volatile("cp.async.commit_group;" ::: "memory")
#define CPWAIT0()  asm volatile("cp.async.wait_group 0;" ::: "memory")

__device__ __forceinline__ uint32_t packf16(float2 s) {
    uint32_t r;   // lo half = s.x
    asm("cvt.rn.f16x2.f32 %0, %1, %2;" : "=r"(r) : "f"(s.y), "f"(s.x));
    return r;
}
__device__ __forceinline__ uint32_t hsub2(uint32_t a, uint32_t b) {
    uint32_t d;
    asm("sub.rn.f16x2 %0, %1, %2;" : "=r"(d) : "r"(a), "r"(b));
    return d;
}
__device__ __forceinline__ uint32_t hfma2(uint32_t a, uint32_t b, uint32_t c) {
    uint32_t d;
    asm("fma.rn.f16x2 %0, %1, %2, %3;" : "=r"(d) : "r"(a), "r"(b), "r"(c));
    return d;
}
__device__ __forceinline__ uint32_t duplo(uint32_t a) {
    uint32_t d;
    asm("prmt.b32 %0, %1, %1, 0x1010;" : "=r"(d) : "r"(a));
    return d;
}
__device__ __forceinline__ uint32_t duphi(uint32_t a) {
    uint32_t d;
    asm("prmt.b32 %0, %1, %1, 0x3232;" : "=r"(d) : "r"(a));
    return d;
}
__device__ __forceinline__ float h2lof(uint32_t h) {
    __half2 v = *(__half2*)&h;
    return __low2float(v);
}
__device__ __forceinline__ void mma16(float* d,
                                      uint32_t a0, uint32_t a1, uint32_t a2, uint32_t a3,
                                      uint32_t b0, uint32_t b1) {
    asm volatile(
        "mma.sync.aligned.m16n8k16.row.col.f32.f16.f16.f32 "
        "{%0,%1,%2,%3}, {%4,%5,%6,%7}, {%8,%9}, {%0,%1,%2,%3};"
        : "+f"(d[0]), "+f"(d[1]), "+f"(d[2]), "+f"(d[3])
        : "r"(a0), "r"(a1), "r"(a2), "r"(a3), "r"(b0), "r"(b1));
}

// bilinear sample of channel quad `tig` at interleaved-tile position `val`.
// Tile layout: [pos][16 ch] (4 uint2 per pos); xq = tile base (uint2*) + tig.
__device__ __forceinline__ uint2 bsq(const uint2* __restrict__ xq,
                                     const float* __restrict__ xgq,
                                     uint2 m) {
    int val = (int)m.y;
    uint32_t wyd = duplo(m.x), wxd = duphi(m.x);
    if (val >= 0) {
        int i0 = val * 4;
        uint2 c0 = xq[i0], c1 = xq[i0 + 4];
        uint2 c2 = xq[i0 + 120], c3 = xq[i0 + 124];
        uint32_t rx0 = hfma2(hsub2(c1.x, c0.x), wxd, c0.x);
        uint32_t rx1 = hfma2(hsub2(c3.x, c2.x), wxd, c2.x);
        uint32_t ry0 = hfma2(hsub2(c1.y, c0.y), wxd, c0.y);
        uint32_t ry1 = hfma2(hsub2(c3.y, c2.y), wxd, c2.y);
        uint2 r;
        r.x = hfma2(hsub2(rx1, rx0), wyd, rx0);
        r.y = hfma2(hsub2(ry1, ry0), wyd, ry0);
        return r;
    }
    // rare fallback: fp32 masked global bilinear on 4 channels
    float wy = h2lof(wyd), wx = h2lof(wxd);
    float oy = 1.f - wy, ox = 1.f - wx;
    float w00 = oy * ox, w01 = oy * wx, w10 = wy * ox, w11 = wy * wx;
    int iy = ((val >> 8) & 0xff) - 2;
    int ix = (val & 0xff) - 2;
    bool m00 = ((unsigned)iy < 128u) & ((unsigned)ix < 128u);
    bool m01 = ((unsigned)iy < 128u) & ((unsigned)(ix + 1) < 128u);
    bool m10 = ((unsigned)(iy + 1) < 128u) & ((unsigned)ix < 128u);
    bool m11 = ((unsigned)(iy + 1) < 128u) & ((unsigned)(ix + 1) < 128u);
    int i00 = iy * 128 + ix;
    float v[4];
#pragma unroll
    for (int c = 0; c < 4; c++) {
        const float* g = xgq + c * 16384;
        v[c] = w00 * (m00 ? g[i00] : 0.f) + w01 * (m01 ? g[i00 + 1] : 0.f)
             + w10 * (m10 ? g[i00 + 128] : 0.f) + w11 * (m11 ? g[i00 + 129] : 0.f);
    }
    uint2 r;
    r.x = packf16(make_float2(v[0], v[1]));
    r.y = packf16(make_float2(v[2], v[3]));
    return r;
}

// ===================== wprep: weight layouts (own launch; no races) =========
__global__ void wprep_kernel(const float* __restrict__ dw,
                             const float* __restrict__ ow) {
    int i = blockIdx.x * 256 + threadIdx.x;
    if (i < 9216) {            // main W: chunk ^ tig swizzle
        int j = i / 2304, r = i - j * 2304;
        int t = r >> 8, r2 = r & 255;
        int tg = r2 >> 6, r3 = r2 & 63;
        int gd = r3 >> 3, ntp = r3 & 7;
        int k = (ntp >> 1) ^ tg;
        int nt = (k << 1) | (ntp & 1);
        int o = nt * 8 + gd;
        int c0 = j * 16 + 4 * tg;
        __half2 h0 = __floats2half2_rn(dw[o * 576 + c0 * 9 + t],
                                       dw[o * 576 + (c0 + 1) * 9 + t]);
        __half2 h1 = __floats2half2_rn(dw[o * 576 + (c0 + 2) * 9 + t],
                                       dw[o * 576 + (c0 + 3) * 9 + t]);
        uint2 v;
        v.x = *(uint32_t*)&h0;
        v.y = *(uint32_t*)&h1;
        g_w16m[i] = v;
    }
    if (i < 4608) {            // offset W
        int j = i / 1152, r = i - j * 1152;
        int t = r >> 7, r2 = r & 127;
        int tg = r2 >> 5, r3 = r2 & 31;
        int gd = r3 >> 2, nt = r3 & 3;
        int o = nt * 8 + gd;
        int c0 = j * 16 + 4 * tg;
        float w0 = 0.f, w1 = 0.f, w2 = 0.f, w3 = 0.f;
        if (o < 18) {
            w0 = ow[o * 576 + c0 * 9 + t];
            w1 = ow[o * 576 + (c0 + 1) * 9 + t];
            w2 = ow[o * 576 + (c0 + 2) * 9 + t];
            w3 = ow[o * 576 + (c0 + 3) * 9 + t];
        }
        uint2 v;
        v.x = packf16(make_float2(w0, w1));
        v.y = packf16(make_float2(w2, w3));
        g_ow16[i] = v;
    }
}

// ===================== fused prep: offconv + xpack =====================
// blocks [0,512): offconv; [512,2560): xpack
__global__ __launch_bounds__(256, 2) void prep_kernel(
    const float* __restrict__ x, const float* __restrict__ ob)
{
    __shared__ __align__(16) char psm[19584];
    int id = blockIdx.x;
    int tid = threadIdx.x;

    if (id >= 512) {             // ---- xpack ----
        uint32_t* sm = (uint32_t*)psm;       // [pixel][c2] 64x32
        int id2 = id - 512;
        int bp = (id2 & 255) * 64;
        int b = id2 >> 8;
        const float* xb = x + (size_t)b * 64 * 16384;
        for (int i = tid; i < 2048; i += 256) {
            int c2 = i >> 6, p = i & 63;
            float v0 = xb[(2 * c2) * 16384 + bp + p];
            float v1 = xb[(2 * c2 + 1) * 16384 + bp + p];
            sm[p * 32 + c2] = packf16(make_float2(v0, v1));
        }
        __syncthreads();
        uint4* dst = (uint4*)(g_xp + ((size_t)b * 16384 + bp) * 64);
        const uint4* src = (const uint4*)sm;
        for (int i = tid; i < 512; i += 256) dst[i] = src[i];
        return;
    }

    // ---- offconv (R12/R15-validated) ----
    uint2* xtq = (uint2*)psm;                // [quad][18x18] 1296
    uint2* wh  = (uint2*)(psm + 10368);      // [t][tig][gid][nt4] 1152

    int w = tid >> 5, lane = tid & 31;
    int gid = lane >> 2, tig = lane & 3;
    int bx = id & 7, by = (id >> 3) & 7, b = id >> 6;
    int ty = by * 16, tx = bx * 16;
    const float* xb = x + (size_t)b * 64 * 16384;

    float acc0[3][4], acc1[3][4];
#pragma unroll
    for (int n = 0; n < 3; n++)
#pragma unroll
        for (int i = 0; i < 4; i++) { acc0[n][i] = 0.f; acc1[n][i] = 0.f; }

    for (int j = 0; j < 4; j++) {
        __syncthreads();
        const float* xc = xb + (size_t)j * 16 * 16384;
        for (int t = tid; t < 1296; t += 256) {
            int q = t / 324, pos = t - q * 324;
            int rr = pos / 18, cl = pos - rr * 18;
            int gy = ty - 1 + rr, gx = tx - 1 + cl;
            uint2 v = make_uint2(0u, 0u);
            if ((unsigned)gy < 128u && (unsigned)gx < 128u) {
                const float* s = xc + 4 * q * 16384 + gy * 128 + gx;
                v.x = packf16(make_float2(s[0], s[16384]));
                v.y = packf16(make_float2(s[2 * 16384], s[3 * 16384]));
            }
            xtq[t] = v;
        }
        for (int t = tid; t < 1152; t += 256) wh[t] = g_ow16[j * 1152 + t];
        __syncthreads();

#pragma unroll
        for (int t9 = 0; t9 < 9; t9++) {
            int dty = t9 / 3, dtx = t9 - dty * 3;
            const uint2* ap = xtq + tig * 324 + (2 * w + dty) * 18 + gid + dtx;
            uint2 A0 = ap[0], A1 = ap[8], A2 = ap[18], A3 = ap[26];

            const uint2* Bp = wh + ((t9 * 4 + tig) * 8 + gid) * 4;
            uint4 q01 = *(const uint4*)Bp;
            uint2 q2 = Bp[2];

            mma16(acc0[0], A0.x, A1.x, A0.y, A1.y, q01.x, q01.y);
            mma16(acc1[0], A2.x, A3.x, A2.y, A3.y, q01.x, q01.y);
            mma16(acc0[1], A0.x, A1.x, A0.y, A1.y, q01.z, q01.w);
            mma16(acc1[1], A2.x, A3.x, A2.y, A3.y, q01.z, q01.w);
            mma16(acc0[2], A0.x, A1.x, A0.y, A1.y, q2.x, q2.y);
            mma16(acc1[2], A2.x, A3.x, A2.y, A3.y, q2.x, q2.y);
        }
    }

    int yA = ty + 2 * w, xA = tx + gid, xB = xA + 8;
    size_t bb = (size_t)b * 18 * 16384;
#pragma unroll
    for (int nt = 0; nt < 3; nt++) {
        int o0 = nt * 8 + 2 * tig;
        if (o0 < 18) {
            float bs = ob[o0];
            float* pl = g_off + bb + (size_t)o0 * 16384;
            pl[yA * 128 + xA]       = acc0[nt][0] + bs;
            pl[yA * 128 + xB]       = acc0[nt][2] + bs;
            pl[(yA + 1) * 128 + xA] = acc1[nt][0] + bs;
            pl[(yA + 1) * 128 + xB] = acc1[nt][2] + bs;
        }
        if (o0 + 1 < 18) {
            float bs = ob[o0 + 1];
            float* pl = g_off + bb + (size_t)(o0 + 1) * 16384;
            pl[yA * 128 + xA]       = acc0[nt][1] + bs;
            pl[yA * 128 + xB]       = acc0[nt][3] + bs;
            pl[(yA + 1) * 128 + xA] = acc1[nt][1] + bs;
            pl[(yA + 1) * 128 + xB] = acc1[nt][3] + bs;
        }
    }
}

// ===================== SMEM layout main (float index) =====================
// smeta : 2304 x uint2, reordered [t][w][gid][q]           [0, 4608)
// tile0 : 870 pos x 32B interleaved                        [4608, 11568)
// tile1 :                                                  [11568, 18528)
// W0    : 2304 uint2 (FULL chunk, 18432 B)                 [18528, 23136)
// W1    :                                                  [23136, 27744)
#define SM_MT  0
#define SM_XT0 4608
#define SM_XT1 11568
#define SM_WH0 18528
#define SM_WH1 23136
#define SMEM_MAIN_BYTES (27744 * 4)

// ===================== stage 2: quad gather + fp16 mma16, cp.async pipe ====
__global__ __launch_bounds__(256, 2) void deform_main_kernel(
    const float* __restrict__ x, const float* __restrict__ db,
    float* __restrict__ out)
{
    extern __shared__ __align__(16) float smf[];
    uint2* smeta = (uint2*)(smf + SM_MT);

    int tid = threadIdx.x, w = tid >> 5, lane = tid & 31;
    int gid = lane >> 2, tig = lane & 3;
    int b = blockIdx.z, ty = blockIdx.y * 16, tx = blockIdx.x * 16;
    const float* xb = x + (size_t)b * 64 * 16384;
    const __half* xpb = g_xp + (size_t)b * 16384 * 64;

    const uint32_t tbu[2] = { smem_u32(smf + SM_XT0), smem_u32(smf + SM_XT1) };
    const uint32_t wbu[2] = { smem_u32(smf + SM_WH0), smem_u32(smf + SM_WH1) };

    auto stage = [&](int j, int buf) {
        uint32_t tb = tbu[buf];
        for (int t = tid; t < 870; t += 256) {
            int rr = t / 30, cl = t - rr * 30;
            int gy = ty - 6 + rr, gx = tx - 6 + cl;
            bool ok = ((unsigned)gy < 128u) && ((unsigned)gx < 128u);
            int pix = ok ? (gy * 128 + gx) : 0;
            const __half* src = xpb + (size_t)pix * 64 + j * 16;
            int sz = ok ? 16 : 0;
            CP16(tb + t * 32, src, sz);
            CP16(tb + t * 32 + 16, src + 8, sz);
        }
        uint32_t wb = wbu[buf];
        const char* wsrc = (const char*)(g_w16m + j * 2304);
        for (int t = tid; t < 1152; t += 256)
            CP16(wb + t * 16, wsrc + t * 16, 16);
        CPCOMMIT();
    };

    stage(0, 0);   // overlaps with metadata prologue below

    // ---- prologue: per (tap,pixel) compact metadata, reordered layout ----
    for (int e = tid; e < 2304; e += 256) {
        int k = e >> 8, p = e & 255;
        int yy = ty + (p >> 4), xx = tx + (p & 15);
        float dy = g_off[((size_t)b * 18 + 2 * k) * 16384 + yy * 128 + xx];
        float dx = g_off[((size_t)b * 18 + 2 * k + 1) * 16384 + yy * 128 + xx];
        float py = (float)(yy + k / 3 - 1) + dy;
        float px = (float)(xx + k % 3 - 1) + dx;
        float fy = floorf(py), fx = floorf(px);
        float wy = py - fy, wx = px - fx;
        int iy = (int)fminf(fmaxf(fy, -2.f), 128.f);
        int ix = (int)fminf(fmaxf(fx, -2.f), 128.f);
        int ly = iy - (ty - 6), lx = ix - (tx - 6);
        int val;
        if ((unsigned)ly < 28u && (unsigned)lx < 29u)
            val = ly * 30 + lx;
        else
            val = (int)(0x80000000u | ((unsigned)(iy + 2) << 8) | (unsigned)(ix + 2));
        int wp = p >> 5, gidp = p & 7, q = (p >> 3) & 3;
        smeta[((k * 8 + wp) * 8 + gidp) * 4 + q] =
            make_uint2(packf16(make_float2(wy, wx)), (uint32_t)val);
    }

    float acc0[8][4], acc1[8][4];
#pragma unroll
    for (int n = 0; n < 8; n++)
#pragma unroll
        for (int i = 0; i < 4; i++) { acc0[n][i] = 0.f; acc1[n][i] = 0.f; }

    CPWAIT0();
    __syncthreads();

    for (int j = 0; j < 4; j++) {
        int buf = j & 1;
        if (j < 3) stage(j + 1, buf ^ 1);

        const uint2* xq = (const uint2*)(smf + (buf ? SM_XT1 : SM_XT0)) + tig;
        const uint2* whs = (const uint2*)(smf + (buf ? SM_WH1 : SM_WH0));
        const float* xgq = xb + (size_t)j * 16 * 16384 + (size_t)(4 * tig) * 16384;

#pragma unroll
        for (int t = 0; t < 9; t++) {
            const uint4* mp = (const uint4*)(smeta + ((t * 8 + w) * 8 + gid) * 4);
            uint4 mA = mp[0], mB = mp[1];
            uint2 A0 = bsq(xq, xgq, make_uint2(mA.x, mA.y));
            uint2 A1 = bsq(xq, xgq, make_uint2(mA.z, mA.w));
            uint2 A2 = bsq(xq, xgq, make_uint2(mB.x, mB.y));
            uint2 A3 = bsq(xq, xgq, make_uint2(mB.z, mB.w));

            // B reads: chunk k lives at physical chunk k ^ tig (bank-despread)
            const uint4* Bp = (const uint4*)(whs + ((t * 4 + tig) * 8 + gid) * 8);
            uint4 q0 = Bp[tig];
            uint4 q1 = Bp[1 ^ tig];
            uint4 q2 = Bp[2 ^ tig];
            uint4 q3 = Bp[3 ^ tig];

            mma16(acc0[0], A0.x, A1.x, A0.y, A1.y, q0.x, q0.y);
            mma16(acc1[0], A2.x, A3.x, A2.y, A3.y, q0.x, q0.y);
            mma16(acc0[1], A0.x, A1.x, A0.y, A1.y, q0.z, q0.w);
            mma16(acc1[1], A2.x, A3.x, A2.y, A3.y, q0.z, q0.w);
            mma16(acc0[2], A0.x, A1.x, A0.y, A1.y, q1.x, q1.y);
            mma16(acc1[2], A2.x, A3.x, A2.y, A3.y, q1.x, q1.y);
            mma16(acc0[3], A0.x, A1.x, A0.y, A1.y, q1.z, q1.w);
            mma16(acc1[3], A2.x, A3.x, A2.y, A3.y, q1.z, q1.w);
            mma16(acc0[4], A0.x, A1.x, A0.y, A1.y, q2.x, q2.y);
            mma16(acc1[4], A2.x, A3.x, A2.y, A3.y, q2.x, q2.y);
            mma16(acc0[5], A0.x, A1.x, A0.y, A1.y, q2.z, q2.w);
            mma16(acc1[5], A2.x, A3.x, A2.y, A3.y, q2.z, q2.w);
            mma16(acc0[6], A0.x, A1.x, A0.y, A1.y, q3.x, q3.y);
            mma16(acc1[6], A2.x, A3.x, A2.y, A3.y, q3.x, q3.y);
            mma16(acc0[7], A0.x, A1.x, A0.y, A1.y, q3.z, q3.w);
            mma16(acc1[7], A2.x, A3.x, A2.y, A3.y, q3.z, q3.w);
        }

        if (j < 3) {
            CPWAIT0();
            __syncthreads();
        }
    }

    // ---- epilogue: bias + relu ----
    int yA = ty + 2 * w, xA = tx + gid, xB = xA + 8;
    float* obp = out + (size_t)b * 64 * 16384;
#pragma unroll
    for (int nt = 0; nt < 8; nt++) {
        int o0 = nt * 8 + 2 * tig;
        float bs0 = db[o0], bs1 = db[o0 + 1];
        float* pl0 = obp + (size_t)o0 * 16384;
        float* pl1 = pl0 + 16384;
        pl0[yA * 128 + xA]       = fmaxf(acc0[nt][0] + bs0, 0.f);
        pl1[yA * 128 + xA]       = fmaxf(acc0[nt][1] + bs1, 0.f);
        pl0[yA * 128 + xB]       = fmaxf(acc0[nt][2] + bs0, 0.f);
        pl1[yA * 128 + xB]       = fmaxf(acc0[nt][3] + bs1, 0.f);
        pl0[(yA + 1) * 128 + xA] = fmaxf(acc1[nt][0] + bs0, 0.f);
        pl1[(yA + 1) * 128 + xA] = fmaxf(acc1[nt][1] + bs1, 0.f);
        pl0[(yA + 1) * 128 + xB] = fmaxf(acc1[nt][2] + bs0, 0.f);
        pl1[(yA + 1) * 128 + xB] = fmaxf(acc1[nt][3] + bs1, 0.f);
    }
}

// ===================== launch =====================
extern "C" void kernel_launch(void* const* d_in, const int* in_sizes, int n_in,
                              void* d_out, int out_size) {
    const float* x        = (const float*)d_in[0];  // (8,64,128,128)
    const float* offset_w = (const float*)d_in[1];  // (18,64,3,3)
    const float* offset_b = (const float*)d_in[2];  // (18,)
    const float* deform_w = (const float*)d_in[3];  // (64,64,3,3)
    const float* deform_b = (const float*)d_in[4];  // (64,)
    float* out = (float*)d_out;                     // (8,64,128,128)

    cudaFuncSetAttribute(deform_main_kernel,
                         cudaFuncAttributeMaxDynamicSharedMemorySize,
                         SMEM_MAIN_BYTES);

    wprep_kernel<<<36, 256>>>(deform_w, offset_w);
    prep_kernel<<<2560, 256>>>(x, offset_b);
    deform_main_kernel<<<dim3(8, 8, 8), 256, SMEM_MAIN_BYTES>>>(x, deform_b, out);
}